// round 8
// baseline (speedup 1.0000x reference)
#include <cuda_runtime.h>
#include <math.h>

#define B_SAMPLES 16384
#define EMB 64

__device__ int g_p_off[B_SAMPLES + 1];
__device__ int g_w_off[B_SAMPLES + 1];

// Boundary-scan offsets: for sorted seg, off[v] = lower_bound(seg, v).
__device__ __forceinline__ void scan_one(const int* __restrict__ seg, int T,
                                         int* __restrict__ off, int i)
{
    int cur = __ldg(seg + i);
    int prev = (i == 0) ? -1 : __ldg(seg + i - 1);
    for (int v = prev + 1; v <= cur; v++) off[v] = i;
    if (i == T - 1) {
        for (int v = cur + 1; v <= B_SAMPLES; v++) off[v] = T;
    }
}

__global__ void __launch_bounds__(256) offsets_kernel(
    const int* __restrict__ p_seg, int TP,
    const int* __restrict__ w_seg, int TW)
{
    int t = blockIdx.x * blockDim.x + threadIdx.x;
    if (t < TP) {
        scan_one(p_seg, TP, g_p_off, t);
    } else if (t < TP + TW) {
        scan_one(w_seg, TW, g_w_off, t - TP);
    }
}

// Warp gather: coalesced idx load + shfl broadcast; 8 independent row loads
// in flight per step (MLP=8). (R5 version, unchanged — 40 regs, best measured.)
__device__ __forceinline__ void gather_shfl(
    const int* __restrict__ idx, int s, int e,
    const float2* __restrict__ t2, int lane,
    float& ax, float& ay)
{
    float sx[8], sy[8];
    #pragma unroll
    for (int k = 0; k < 8; k++) { sx[k] = 0.f; sy[k] = 0.f; }

    int i = s;
    while (i + 32 <= e) {
        int c = __ldg(idx + i + lane);
        #pragma unroll
        for (int k0 = 0; k0 < 32; k0 += 8) {
            int r[8];
            #pragma unroll
            for (int k = 0; k < 8; k++)
                r[k] = __shfl_sync(0xFFFFFFFFu, c, k0 + k);
            float2 v[8];
            #pragma unroll
            for (int k = 0; k < 8; k++)
                v[k] = __ldg(t2 + (size_t)r[k] * 32 + lane);
            #pragma unroll
            for (int k = 0; k < 8; k++) { sx[k] += v[k].x; sy[k] += v[k].y; }
        }
        i += 32;
    }

    const int rem = e - i;
    if (rem > 0) {
        int pos = i + (lane < rem ? lane : rem - 1);   // clamp: in-bounds
        int c = __ldg(idx + pos);
        int k = 0;
        for (; k + 8 <= rem; k += 8) {
            int r[8];
            #pragma unroll
            for (int j = 0; j < 8; j++)
                r[j] = __shfl_sync(0xFFFFFFFFu, c, k + j);
            float2 v[8];
            #pragma unroll
            for (int j = 0; j < 8; j++)
                v[j] = __ldg(t2 + (size_t)r[j] * 32 + lane);
            #pragma unroll
            for (int j = 0; j < 8; j++) { sx[j] += v[j].x; sy[j] += v[j].y; }
        }
        for (; k < rem; k++) {
            int r = __shfl_sync(0xFFFFFFFFu, c, k);
            float2 v = __ldg(t2 + (size_t)r * 32 + lane);
            sx[0] += v.x; sy[0] += v.y;
        }
    }

    ax = ((sx[0] + sx[1]) + (sx[2] + sx[3])) + ((sx[4] + sx[5]) + (sx[6] + sx[7]));
    ay = ((sy[0] + sy[1]) + (sy[2] + sy[3])) + ((sy[4] + sy[5]) + (sy[6] + sy[7]));
}

// Persistent kernel: one resident wave of warps, each striding over samples.
__global__ void __launch_bounds__(256) svdpp_kernel(
    const int* __restrict__ sci_ids,
    const int* __restrict__ pap_ids,
    const int* __restrict__ p_idx,
    const int* __restrict__ w_idx,
    const float* __restrict__ s_fact,
    const float* __restrict__ p_fact,
    const float* __restrict__ s_bias,
    const float* __restrict__ p_bias,
    const float* __restrict__ imp_fact,
    const float* __restrict__ imp_wish,
    const float* __restrict__ g_bias,
    float* __restrict__ out,
    int total_warps)
{
    const int warp0 = (blockIdx.x * blockDim.x + threadIdx.x) >> 5;
    const int lane = threadIdx.x & 31;

    for (int b = warp0; b < B_SAMPLES; b += total_warps) {
        const int ps = g_p_off[b];
        const int pe = g_p_off[b + 1];
        const int ws = g_w_off[b];
        const int we = g_w_off[b + 1];

        const int sid = __ldg(sci_ids + b);
        const int pid = __ldg(pap_ids + b);
        float2 se = __ldg(reinterpret_cast<const float2*>(s_fact) + (size_t)sid * 32 + lane);
        float2 pv = __ldg(reinterpret_cast<const float2*>(p_fact) + (size_t)pid * 32 + lane);

        float px = 0.f, py = 0.f;
        gather_shfl(p_idx, ps, pe,
                    reinterpret_cast<const float2*>(imp_fact), lane, px, py);
        const float pscale = rsqrtf(fmaxf((float)(pe - ps), 1.0f));

        float wx = 0.f, wy = 0.f;
        gather_shfl(w_idx, ws, we,
                    reinterpret_cast<const float2*>(imp_wish), lane, wx, wy);
        const float wscale = rsqrtf(fmaxf((float)(we - ws), 1.0f));

        const float yx = px * pscale + wx * wscale;
        const float yy = py * pscale + wy * wscale;

        float d = (se.x + yx) * pv.x + (se.y + yy) * pv.y;

        #pragma unroll
        for (int off = 16; off > 0; off >>= 1)
            d += __shfl_xor_sync(0xFFFFFFFFu, d, off);

        if (lane == 0) {
            out[b] = d + __ldg(s_bias + sid) + __ldg(p_bias + pid) + __ldg(g_bias);
        }
    }
}

extern "C" void kernel_launch(void* const* d_in, const int* in_sizes, int n_in,
                              void* d_out, int out_size)
{
    const int*   sci_ids = (const int*)d_in[0];
    const int*   pap_ids = (const int*)d_in[1];
    const int*   p_idx   = (const int*)d_in[2];
    const int*   p_seg   = (const int*)d_in[3];
    const int*   w_idx   = (const int*)d_in[4];
    const int*   w_seg   = (const int*)d_in[5];
    const float* s_fact  = (const float*)d_in[6];
    const float* p_fact  = (const float*)d_in[7];
    const float* s_bias  = (const float*)d_in[8];
    const float* p_bias  = (const float*)d_in[9];
    const float* imp_f   = (const float*)d_in[10];
    const float* imp_w   = (const float*)d_in[11];
    const float* g_bias  = (const float*)d_in[12];
    float* out = (float*)d_out;

    const int TP = in_sizes[2];
    const int TW = in_sizes[4];

    // Pass 1: boundary-scan segment offsets (one thread per idx element).
    const int total = TP + TW;
    offsets_kernel<<<(total + 255) / 256, 256>>>(p_seg, TP, w_seg, TW);

    // Pass 2: persistent — one wave of resident warps striding over samples.
    // 148 SMs x 6 blocks (256 thr, ~40 regs -> 1536 thr/SM resident).
    const int blocks = 148 * 6;
    const int total_warps = blocks * (256 / 32);
    svdpp_kernel<<<blocks, 256>>>(
        sci_ids, pap_ids, p_idx, w_idx,
        s_fact, p_fact, s_bias, p_bias, imp_f, imp_w, g_bias, out,
        total_warps);
}